// round 1
// baseline (speedup 1.0000x reference)
#include <cuda_runtime.h>
#include <math.h>

#define NN 50000
#define NE 1600000
#define HD 16

// ---------------- scratch (device globals; no allocs allowed) ----------------
__device__ float g_h[NN * HD];      // current layer transformed features h = x @ W
__device__ float g_as[NN];          // per-node  h . att_src
__device__ float g_ad[NN];          // per-node  h . att_dst
__device__ float g_acc[NN * HD];    // unnormalized aggregation  sum_e w_e * h[src_e]
__device__ float g_denom[NN];       // sum_e w_e
__device__ float g_A[NN * HD];      // edge-MLP precompute: x2 @ Wm1[0:16]
__device__ float g_B[NN * HD];      // edge-MLP precompute: x2 @ Wm1[16:32] + bm1

__device__ __forceinline__ float lrelu(float x) { return x > 0.f ? x : 0.2f * x; }
__device__ __forceinline__ float gelu_exact(float x) {
    return 0.5f * x * (1.f + erff(x * 0.70710678118654752440f));
}
__device__ __forceinline__ void red_add_v4(float* p, float4 v) {
    asm volatile("red.global.add.v4.f32 [%0], {%1,%2,%3,%4};"
                 :: "l"(p), "f"(v.x), "f"(v.y), "f"(v.z), "f"(v.w) : "memory");
}

// ---------------- layer 1 node kernel: h1 = node_emb @ W1, self-loop init ----
__global__ void k_node1(const float* __restrict__ node_emb,
                        const float* __restrict__ W1,
                        const float* __restrict__ att_s,
                        const float* __restrict__ att_d) {
    __shared__ float sW[64 * HD];
    __shared__ float sas[HD], sad[HD];
    for (int i = threadIdx.x; i < 64 * HD; i += blockDim.x) sW[i] = W1[i];
    if (threadIdx.x < HD) { sas[threadIdx.x] = att_s[threadIdx.x]; sad[threadIdx.x] = att_d[threadIdx.x]; }
    __syncthreads();

    int n = blockIdx.x * blockDim.x + threadIdx.x;
    if (n >= NN) return;

    float h[HD];
#pragma unroll
    for (int j = 0; j < HD; j++) h[j] = 0.f;

    const float4* xe = (const float4*)(node_emb + (size_t)n * 64);
#pragma unroll
    for (int k4 = 0; k4 < 16; k4++) {
        float4 v = xe[k4];
        int k = k4 * 4;
#pragma unroll
        for (int j = 0; j < HD; j++) {
            h[j] += v.x * sW[(k + 0) * HD + j];
            h[j] += v.y * sW[(k + 1) * HD + j];
            h[j] += v.z * sW[(k + 2) * HD + j];
            h[j] += v.w * sW[(k + 3) * HD + j];
        }
    }
    float as = 0.f, ad = 0.f;
#pragma unroll
    for (int j = 0; j < HD; j++) { as += h[j] * sas[j]; ad += h[j] * sad[j]; }

    float w = expf(lrelu(as + ad));   // self-loop weight (no max-shift: logits tiny)
    g_as[n] = as; g_ad[n] = ad; g_denom[n] = w;

    float4* hp = (float4*)(g_h + n * HD);
    float4* ap = (float4*)(g_acc + n * HD);
#pragma unroll
    for (int q = 0; q < 4; q++) {
        float4 hv = make_float4(h[q*4+0], h[q*4+1], h[q*4+2], h[q*4+3]);
        hp[q] = hv;
        ap[q] = make_float4(w * hv.x, w * hv.y, w * hv.z, w * hv.w);
    }
}

// ---------------- edge aggregation (both layers): unnormalized scatter ------
__global__ void k_edge_agg(const int* __restrict__ src, const int* __restrict__ dst) {
    int e = blockIdx.x * blockDim.x + threadIdx.x;
    if (e >= NE) return;
    int s = src[e], d = dst[e];
    float w = expf(lrelu(g_as[s] + g_ad[d]));
    atomicAdd(&g_denom[d], w);
    const float4* hs = (const float4*)(g_h + s * HD);
    float* ac = g_acc + d * HD;
#pragma unroll
    for (int q = 0; q < 4; q++) {
        float4 v = hs[q];
        red_add_v4(ac + q * 4, make_float4(w * v.x, w * v.y, w * v.z, w * v.w));
    }
}

// ---------------- layer 2 node kernel: finish layer1, start layer2 ----------
__global__ void k_node2(const float* __restrict__ W2,
                        const float* __restrict__ b1,
                        const float* __restrict__ att_s,
                        const float* __restrict__ att_d) {
    __shared__ float sW[HD * HD];
    __shared__ float sb[HD], sas[HD], sad[HD];
    for (int i = threadIdx.x; i < HD * HD; i += blockDim.x) sW[i] = W2[i];
    if (threadIdx.x < HD) {
        sb[threadIdx.x] = b1[threadIdx.x];
        sas[threadIdx.x] = att_s[threadIdx.x];
        sad[threadIdx.x] = att_d[threadIdx.x];
    }
    __syncthreads();

    int n = blockIdx.x * blockDim.x + threadIdx.x;
    if (n >= NN) return;

    float inv_d = 1.f / g_denom[n];
    float x[HD];
#pragma unroll
    for (int j = 0; j < HD; j++)
        x[j] = gelu_exact(g_acc[n * HD + j] * inv_d + sb[j]);

    float h[HD];
#pragma unroll
    for (int j = 0; j < HD; j++) h[j] = 0.f;
#pragma unroll
    for (int k = 0; k < HD; k++) {
        float xv = x[k];
#pragma unroll
        for (int j = 0; j < HD; j++) h[j] += xv * sW[k * HD + j];
    }
    float as = 0.f, ad = 0.f;
#pragma unroll
    for (int j = 0; j < HD; j++) { as += h[j] * sas[j]; ad += h[j] * sad[j]; }

    float w = expf(lrelu(as + ad));
    g_as[n] = as; g_ad[n] = ad; g_denom[n] = w;

    float4* hp = (float4*)(g_h + n * HD);
    float4* ap = (float4*)(g_acc + n * HD);
#pragma unroll
    for (int q = 0; q < 4; q++) {
        float4 hv = make_float4(h[q*4+0], h[q*4+1], h[q*4+2], h[q*4+3]);
        hp[q] = hv;
        ap[q] = make_float4(w * hv.x, w * hv.y, w * hv.z, w * hv.w);
    }
}

// ---------------- node kernel 3: finish layer2, precompute edge-MLP A/B -----
__global__ void k_node3(const float* __restrict__ Wm1,
                        const float* __restrict__ b2,
                        const float* __restrict__ bm1) {
    __shared__ float sWa[HD * HD];   // Wm1 rows 0..15  (x[src] part)
    __shared__ float sWb[HD * HD];   // Wm1 rows 16..31 (x[dst] part)
    __shared__ float sb2[HD], sbm[HD];
    for (int i = threadIdx.x; i < HD * HD; i += blockDim.x) {
        sWa[i] = Wm1[i];
        sWb[i] = Wm1[HD * HD + i];
    }
    if (threadIdx.x < HD) { sb2[threadIdx.x] = b2[threadIdx.x]; sbm[threadIdx.x] = bm1[threadIdx.x]; }
    __syncthreads();

    int n = blockIdx.x * blockDim.x + threadIdx.x;
    if (n >= NN) return;

    float inv_d = 1.f / g_denom[n];
    float x[HD];
#pragma unroll
    for (int j = 0; j < HD; j++)
        x[j] = gelu_exact(g_acc[n * HD + j] * inv_d + sb2[j]);

    float A[HD], B[HD];
#pragma unroll
    for (int j = 0; j < HD; j++) { A[j] = 0.f; B[j] = sbm[j]; }
#pragma unroll
    for (int k = 0; k < HD; k++) {
        float xv = x[k];
#pragma unroll
        for (int j = 0; j < HD; j++) {
            A[j] += xv * sWa[k * HD + j];
            B[j] += xv * sWb[k * HD + j];
        }
    }
    float4* pa = (float4*)(g_A + n * HD);
    float4* pb = (float4*)(g_B + n * HD);
#pragma unroll
    for (int q = 0; q < 4; q++) {
        pa[q] = make_float4(A[q*4+0], A[q*4+1], A[q*4+2], A[q*4+3]);
        pb[q] = make_float4(B[q*4+0], B[q*4+1], B[q*4+2], B[q*4+3]);
    }
}

// ---------------- final per-edge MLP ----------------------------------------
__global__ void k_edge_mlp(const int* __restrict__ src, const int* __restrict__ dst,
                           const float* __restrict__ edge_emb,
                           const float* __restrict__ Wm1,
                           const float* __restrict__ Wm2,
                           const float* __restrict__ bm2,
                           float* __restrict__ out) {
    __shared__ float sWe[HD * HD];   // Wm1 rows 32..47 (edge_emb part)
    __shared__ float sW2[HD];
    __shared__ float sbm2;
    for (int i = threadIdx.x; i < HD * HD; i += blockDim.x) sWe[i] = Wm1[2 * HD * HD + i];
    if (threadIdx.x < HD) sW2[threadIdx.x] = Wm2[threadIdx.x];
    if (threadIdx.x == 0) sbm2 = bm2[0];
    __syncthreads();

    int e = blockIdx.x * blockDim.x + threadIdx.x;
    if (e >= NE) return;
    int s = src[e], d = dst[e];

    const float4* pa = (const float4*)(g_A + s * HD);
    const float4* pb = (const float4*)(g_B + d * HD);
    const float4* pe = (const float4*)(edge_emb + (size_t)e * HD);

    float hm[HD];
#pragma unroll
    for (int q = 0; q < 4; q++) {
        float4 a = pa[q]; float4 b = pb[q];
        hm[q*4+0] = a.x + b.x; hm[q*4+1] = a.y + b.y;
        hm[q*4+2] = a.z + b.z; hm[q*4+3] = a.w + b.w;
    }
#pragma unroll
    for (int q = 0; q < 4; q++) {
        float4 ev = pe[q];
        int k = q * 4;
#pragma unroll
        for (int j = 0; j < HD; j++) {
            hm[j] += ev.x * sWe[(k + 0) * HD + j];
            hm[j] += ev.y * sWe[(k + 1) * HD + j];
            hm[j] += ev.z * sWe[(k + 2) * HD + j];
            hm[j] += ev.w * sWe[(k + 3) * HD + j];
        }
    }
    float z = sbm2;
#pragma unroll
    for (int j = 0; j < HD; j++) z += fmaxf(hm[j], 0.f) * sW2[j];
    out[e] = 1.f / (1.f + expf(-z));
}

// ---------------- launcher ---------------------------------------------------
extern "C" void kernel_launch(void* const* d_in, const int* in_sizes, int n_in,
                              void* d_out, int out_size) {
    const int*   edge_index = (const int*)d_in[0];
    const float* node_emb   = (const float*)d_in[1];
    const float* edge_emb   = (const float*)d_in[2];
    const float* W1         = (const float*)d_in[3];
    const float* att_src1   = (const float*)d_in[4];
    const float* att_dst1   = (const float*)d_in[5];
    const float* b1         = (const float*)d_in[6];
    const float* W2         = (const float*)d_in[7];
    const float* att_src2   = (const float*)d_in[8];
    const float* att_dst2   = (const float*)d_in[9];
    const float* b2         = (const float*)d_in[10];
    const float* Wm1        = (const float*)d_in[11];
    const float* bm1        = (const float*)d_in[12];
    const float* Wm2        = (const float*)d_in[13];
    const float* bm2        = (const float*)d_in[14];
    float* out = (float*)d_out;

    const int* src = edge_index;
    const int* dst = edge_index + NE;

    dim3 bn(256), gn((NN + 255) / 256);
    dim3 be(256), ge((NE + 255) / 256);

    k_node1<<<gn, bn>>>(node_emb, W1, att_src1, att_dst1);
    k_edge_agg<<<ge, be>>>(src, dst);
    k_node2<<<gn, bn>>>(W2, b1, att_src2, att_dst2);
    k_edge_agg<<<ge, be>>>(src, dst);
    k_node3<<<gn, bn>>>(Wm1, b2, bm1);
    k_edge_mlp<<<ge, be>>>(src, dst, edge_emb, Wm1, Wm2, bm2, out);
}

// round 6
// speedup vs baseline: 1.1855x; 1.1855x over previous
#include <cuda_runtime.h>
#include <math.h>

#define NN 50000
#define NE 1600000
#define HD 16
#define SCAN_BLK 1024
#define NBLK_SCAN ((NN + SCAN_BLK - 1) / SCAN_BLK)   // 49

// ---------------- scratch (device globals) -----------------------------------
__device__ float g_h[NN * HD];      // transformed features h = x @ W
__device__ float g_as[NN];          // h . att_src
__device__ float g_ad[NN];          // h . att_dst
__device__ float g_acc[NN * HD];    // NORMALIZED aggregation (attention output, pre-bias)
__device__ float g_A[NN * HD];      // edge-MLP precompute: x2 @ Wm1[0:16]
__device__ float g_B[NN * HD];      // edge-MLP precompute: x2 @ Wm1[16:32] + bm1
// CSR by dst
__device__ int g_deg[NN];
__device__ int g_off[NN + 1];
__device__ int g_cursor[NN];
__device__ int g_csr_src[NE];
__device__ int g_bsum[NBLK_SCAN];

__device__ __forceinline__ float lrelu(float x) { return x > 0.f ? x : 0.2f * x; }
__device__ __forceinline__ float gelu_exact(float x) {
    return 0.5f * x * (1.f + erff(x * 0.70710678118654752440f));
}

// ---------------- CSR build --------------------------------------------------
__global__ void k_zero_deg() {
    int i = blockIdx.x * blockDim.x + threadIdx.x;
    if (i < NN) g_deg[i] = 0;
}

__global__ void k_count(const int* __restrict__ dst) {
    int e = blockIdx.x * blockDim.x + threadIdx.x;
    if (e < NE) atomicAdd(&g_deg[dst[e]], 1);
}

__global__ void k_scan1() {
    int t = threadIdx.x, b = blockIdx.x;
    int i = b * SCAN_BLK + t;
    int v = (i < NN) ? g_deg[i] : 0;
    int lane = t & 31, wid = t >> 5;
    // warp inclusive scan
    int inc = v;
#pragma unroll
    for (int o = 1; o < 32; o <<= 1) {
        int y = __shfl_up_sync(0xffffffffu, inc, o);
        if (lane >= o) inc += y;
    }
    __shared__ int wsum[32];
    if (lane == 31) wsum[wid] = inc;
    __syncthreads();
    if (wid == 0) {
        int x = wsum[lane];
#pragma unroll
        for (int o = 1; o < 32; o <<= 1) {
            int y = __shfl_up_sync(0xffffffffu, x, o);
            if (lane >= o) x += y;
        }
        wsum[lane] = x;
    }
    __syncthreads();
    int excl = inc - v + (wid > 0 ? wsum[wid - 1] : 0);
    if (i < NN) g_off[i] = excl;
    if (t == SCAN_BLK - 1) g_bsum[b] = excl + v;
}

__global__ void k_scan2() {
    if (threadIdx.x == 0) {
        int run = 0;
        for (int b = 0; b < NBLK_SCAN; b++) { int x = g_bsum[b]; g_bsum[b] = run; run += x; }
    }
}

__global__ void k_scan3() {
    int i = blockIdx.x * blockDim.x + threadIdx.x;
    if (i < NN) {
        int off = g_off[i] + g_bsum[i >> 10];
        g_off[i] = off;
        g_cursor[i] = off;
    }
    if (i == 0) g_off[NN] = NE;
}

__global__ void k_scatter(const int* __restrict__ src, const int* __restrict__ dst) {
    int e = blockIdx.x * blockDim.x + threadIdx.x;
    if (e >= NE) return;
    int pos = atomicAdd(&g_cursor[dst[e]], 1);
    g_csr_src[pos] = src[e];
}

// ---------------- layer 1 node kernel: h1 = node_emb @ W1 --------------------
__global__ void k_node1(const float* __restrict__ node_emb,
                        const float* __restrict__ W1,
                        const float* __restrict__ att_s,
                        const float* __restrict__ att_d) {
    __shared__ float sW[64 * HD];
    __shared__ float sas[HD], sad[HD];
    for (int i = threadIdx.x; i < 64 * HD; i += blockDim.x) sW[i] = W1[i];
    if (threadIdx.x < HD) { sas[threadIdx.x] = att_s[threadIdx.x]; sad[threadIdx.x] = att_d[threadIdx.x]; }
    __syncthreads();

    int n = blockIdx.x * blockDim.x + threadIdx.x;
    if (n >= NN) return;

    float h[HD];
#pragma unroll
    for (int j = 0; j < HD; j++) h[j] = 0.f;

    const float4* xe = (const float4*)(node_emb + (size_t)n * 64);
#pragma unroll
    for (int k4 = 0; k4 < 16; k4++) {
        float4 v = xe[k4];
        int k = k4 * 4;
#pragma unroll
        for (int j = 0; j < HD; j++) {
            h[j] += v.x * sW[(k + 0) * HD + j];
            h[j] += v.y * sW[(k + 1) * HD + j];
            h[j] += v.z * sW[(k + 2) * HD + j];
            h[j] += v.w * sW[(k + 3) * HD + j];
        }
    }
    float as = 0.f, ad = 0.f;
#pragma unroll
    for (int j = 0; j < HD; j++) { as += h[j] * sas[j]; ad += h[j] * sad[j]; }
    g_as[n] = as; g_ad[n] = ad;

    float4* hp = (float4*)(g_h + n * HD);
#pragma unroll
    for (int q = 0; q < 4; q++)
        hp[q] = make_float4(h[q*4+0], h[q*4+1], h[q*4+2], h[q*4+3]);
}

// ---------------- gather aggregation: warp per dst node, no atomics ----------
// 32 lanes = 2 edges x 16 dims per iteration. Writes NORMALIZED result.
__global__ void k_agg() {
    int w = blockIdx.x * (blockDim.x >> 5) + (threadIdx.x >> 5);
    if (w >= NN) return;
    int lane = threadIdx.x & 31;
    int dim = lane & 15;

    float ad = g_ad[w];
    float acc = 0.f, den = 0.f;
    int beg = g_off[w], end = g_off[w + 1];

    for (int i = beg + (lane >> 4); i < end; i += 2) {
        int s = __ldg(&g_csr_src[i]);
        float as = g_as[s];
        float wgt = __expf(lrelu(as + ad));
        acc += wgt * g_h[s * HD + dim];
        den += wgt;
    }
    // combine the two 16-lane sub-groups
    acc += __shfl_xor_sync(0xffffffffu, acc, 16);
    den += __shfl_xor_sync(0xffffffffu, den, 16);

    // self-loop
    float wself = __expf(lrelu(g_as[w] + ad));
    den += wself;
    acc += wself * g_h[w * HD + dim];

    if (lane < HD) g_acc[w * HD + dim] = acc / den;
}

// ---------------- node kernel 2: gelu + layer-2 transform --------------------
__global__ void k_node2(const float* __restrict__ W2,
                        const float* __restrict__ b1,
                        const float* __restrict__ att_s,
                        const float* __restrict__ att_d) {
    __shared__ float sW[HD * HD];
    __shared__ float sb[HD], sas[HD], sad[HD];
    for (int i = threadIdx.x; i < HD * HD; i += blockDim.x) sW[i] = W2[i];
    if (threadIdx.x < HD) {
        sb[threadIdx.x] = b1[threadIdx.x];
        sas[threadIdx.x] = att_s[threadIdx.x];
        sad[threadIdx.x] = att_d[threadIdx.x];
    }
    __syncthreads();

    int n = blockIdx.x * blockDim.x + threadIdx.x;
    if (n >= NN) return;

    float x[HD];
#pragma unroll
    for (int j = 0; j < HD; j++)
        x[j] = gelu_exact(g_acc[n * HD + j] + sb[j]);

    float h[HD];
#pragma unroll
    for (int j = 0; j < HD; j++) h[j] = 0.f;
#pragma unroll
    for (int k = 0; k < HD; k++) {
        float xv = x[k];
#pragma unroll
        for (int j = 0; j < HD; j++) h[j] += xv * sW[k * HD + j];
    }
    float as = 0.f, ad = 0.f;
#pragma unroll
    for (int j = 0; j < HD; j++) { as += h[j] * sas[j]; ad += h[j] * sad[j]; }
    g_as[n] = as; g_ad[n] = ad;

    float4* hp = (float4*)(g_h + n * HD);
#pragma unroll
    for (int q = 0; q < 4; q++)
        hp[q] = make_float4(h[q*4+0], h[q*4+1], h[q*4+2], h[q*4+3]);
}

// ---------------- node kernel 3: finish layer2, precompute edge-MLP A/B ------
__global__ void k_node3(const float* __restrict__ Wm1,
                        const float* __restrict__ b2,
                        const float* __restrict__ bm1) {
    __shared__ float sWa[HD * HD];   // Wm1 rows 0..15  (x[src] part)
    __shared__ float sWb[HD * HD];   // Wm1 rows 16..31 (x[dst] part)
    __shared__ float sb2[HD], sbm[HD];
    for (int i = threadIdx.x; i < HD * HD; i += blockDim.x) {
        sWa[i] = Wm1[i];
        sWb[i] = Wm1[HD * HD + i];
    }
    if (threadIdx.x < HD) { sb2[threadIdx.x] = b2[threadIdx.x]; sbm[threadIdx.x] = bm1[threadIdx.x]; }
    __syncthreads();

    int n = blockIdx.x * blockDim.x + threadIdx.x;
    if (n >= NN) return;

    float x[HD];
#pragma unroll
    for (int j = 0; j < HD; j++)
        x[j] = gelu_exact(g_acc[n * HD + j] + sb2[j]);

    float A[HD], B[HD];
#pragma unroll
    for (int j = 0; j < HD; j++) { A[j] = 0.f; B[j] = sbm[j]; }
#pragma unroll
    for (int k = 0; k < HD; k++) {
        float xv = x[k];
#pragma unroll
        for (int j = 0; j < HD; j++) {
            A[j] += xv * sWa[k * HD + j];
            B[j] += xv * sWb[k * HD + j];
        }
    }
    float4* pa = (float4*)(g_A + n * HD);
    float4* pb = (float4*)(g_B + n * HD);
#pragma unroll
    for (int q = 0; q < 4; q++) {
        pa[q] = make_float4(A[q*4+0], A[q*4+1], A[q*4+2], A[q*4+3]);
        pb[q] = make_float4(B[q*4+0], B[q*4+1], B[q*4+2], B[q*4+3]);
    }
}

// ---------------- final per-edge MLP ----------------------------------------
__global__ void k_edge_mlp(const int* __restrict__ src, const int* __restrict__ dst,
                           const float* __restrict__ edge_emb,
                           const float* __restrict__ Wm1,
                           const float* __restrict__ Wm2,
                           const float* __restrict__ bm2,
                           float* __restrict__ out) {
    __shared__ float sWe[HD * HD];   // Wm1 rows 32..47 (edge_emb part)
    __shared__ float sW2[HD];
    __shared__ float sbm2;
    for (int i = threadIdx.x; i < HD * HD; i += blockDim.x) sWe[i] = Wm1[2 * HD * HD + i];
    if (threadIdx.x < HD) sW2[threadIdx.x] = Wm2[threadIdx.x];
    if (threadIdx.x == 0) sbm2 = bm2[0];
    __syncthreads();

    int e = blockIdx.x * blockDim.x + threadIdx.x;
    if (e >= NE) return;
    int s = src[e], d = dst[e];

    const float4* pa = (const float4*)(g_A + s * HD);
    const float4* pb = (const float4*)(g_B + d * HD);
    const float4* pe = (const float4*)(edge_emb + (size_t)e * HD);

    float hm[HD];
#pragma unroll
    for (int q = 0; q < 4; q++) {
        float4 a = pa[q]; float4 b = pb[q];
        hm[q*4+0] = a.x + b.x; hm[q*4+1] = a.y + b.y;
        hm[q*4+2] = a.z + b.z; hm[q*4+3] = a.w + b.w;
    }
#pragma unroll
    for (int q = 0; q < 4; q++) {
        float4 ev = pe[q];
        int k = q * 4;
#pragma unroll
        for (int j = 0; j < HD; j++) {
            hm[j] += ev.x * sWe[(k + 0) * HD + j];
            hm[j] += ev.y * sWe[(k + 1) * HD + j];
            hm[j] += ev.z * sWe[(k + 2) * HD + j];
            hm[j] += ev.w * sWe[(k + 3) * HD + j];
        }
    }
    float z = sbm2;
#pragma unroll
    for (int j = 0; j < HD; j++) z += fmaxf(hm[j], 0.f) * sW2[j];
    out[e] = 1.f / (1.f + __expf(-z));
}

// ---------------- launcher ---------------------------------------------------
extern "C" void kernel_launch(void* const* d_in, const int* in_sizes, int n_in,
                              void* d_out, int out_size) {
    const int*   edge_index = (const int*)d_in[0];
    const float* node_emb   = (const float*)d_in[1];
    const float* edge_emb   = (const float*)d_in[2];
    const float* W1         = (const float*)d_in[3];
    const float* att_src1   = (const float*)d_in[4];
    const float* att_dst1   = (const float*)d_in[5];
    const float* b1         = (const float*)d_in[6];
    const float* W2         = (const float*)d_in[7];
    const float* att_src2   = (const float*)d_in[8];
    const float* att_dst2   = (const float*)d_in[9];
    const float* b2         = (const float*)d_in[10];
    const float* Wm1        = (const float*)d_in[11];
    const float* bm1        = (const float*)d_in[12];
    const float* Wm2        = (const float*)d_in[13];
    const float* bm2        = (const float*)d_in[14];
    float* out = (float*)d_out;

    const int* src = edge_index;
    const int* dst = edge_index + NE;

    dim3 bn(256), gn((NN + 255) / 256);
    dim3 be(256), ge((NE + 255) / 256);
    dim3 ba(256), ga((NN * 32 + 255) / 256);   // warp per node: 50000 warps

    // CSR build (independent of features)
    k_zero_deg<<<(NN + 1023) / 1024, 1024>>>();
    k_count<<<ge, be>>>(dst);
    k_scan1<<<NBLK_SCAN, SCAN_BLK>>>();
    k_scan2<<<1, 32>>>();
    k_scan3<<<(NN + 1023) / 1024, 1024>>>();
    k_scatter<<<ge, be>>>(src, dst);

    // GAT layer 1
    k_node1<<<gn, bn>>>(node_emb, W1, att_src1, att_dst1);
    k_agg<<<ga, ba>>>();
    // GAT layer 2
    k_node2<<<gn, bn>>>(W2, b1, att_src2, att_dst2);
    k_agg<<<ga, ba>>>();
    // edge MLP
    k_node3<<<gn, bn>>>(Wm1, b2, bm1);
    k_edge_mlp<<<ge, be>>>(src, dst, edge_emb, Wm1, Wm2, bm2, out);
}